// round 15
// baseline (speedup 1.0000x reference)
#include <cuda_runtime.h>
#include <stdint.h>
#include <math.h>

#define Bv 64
#define Sv 256
#define Ev 300
#define Hv 300
#define H2 600
#define G4 1200
#define Rv 512
#define NRELv 46
#define RELDv 50

#define LSTM_BLOCKS_PER_DIR 25   // 12 units (48 gate rows) per block
#define LSTM_THREADS 768         // 24 warps: 4 m-tiles x 6 n-tiles

// lstm smem (floats)
#define KP 304
#define SHSTR 72                 // banks tig*72+grp distinct (R8-proven)
#define SWSTR 56                 // banks tig*56+grp = {0,24,16,8}+grp distinct
#define NROWS 48                 // 4 gates x 12 units
#define SH_OFF 0                              // sH [KP][72]
#define SW_OFF (KP * SHSTR)                   // sW [KP][56]
#define SG_OFF (SW_OFF + KP * SWSTR)          // sG [48][64]
#define SC_OFF (SG_OFF + NROWS * 64)          // sC [12][64]
#define LSTM_SMEM_BYTES ((SC_OFF + 768) * 4)

// mma gemm tile config
#define ASTR 136
#define BSTR 72

// ---------------- device scratch ----------------
__device__ float d_text[Bv * Sv * Ev];
__device__ float d_Xg[2 * Sv * Bv * G4];
__device__ float d_hseq[2 * Sv * Hv * Bv];    // fp32 h (for text_out)
__device__ float d_hseq2[2 * Sv * Hv * Bv];   // tf32-rounded h (for recurrence MMA)
__device__ float d_to[Bv * Sv * H2];
__device__ float d_hid[Bv * Sv * H2];
__device__ float d_x1[Bv * Sv * H2];
__device__ float d_V[NRELv * G4];
__device__ float d_score[Bv * Rv];
__device__ float d_pwv[Bv * Sv];
__device__ float d_xsum[Bv * H2];
__device__ float d_attsc[Bv * Sv];
__device__ float d_alpha[Bv * Sv];
__device__ float d_ov[Bv * H2];
__device__ int d_tlen[Bv], d_alen[Bv], d_llen[Bv];
__device__ unsigned d_barr[2 * Sv];

__device__ __forceinline__ unsigned ld_acquire(const unsigned* p) {
    unsigned v;
    asm volatile("ld.acquire.gpu.global.u32 %0, [%1];" : "=r"(v) : "l"(p) : "memory");
    return v;
}

__device__ __forceinline__ float to_tf32(float x) {
    uint32_t r;
    asm("cvt.rna.tf32.f32 %0, %1;" : "=r"(r) : "f"(x));
    return __uint_as_float(r);
}

// ---------------- barrier reset ----------------
__global__ void barr_reset() {
    int i = threadIdx.x;
    if (i < 2 * Sv) d_barr[i] = 0u;
}

// ---------------- lengths ----------------
__global__ void len_kernel(const int* __restrict__ ti, const int* __restrict__ ai,
                           const int* __restrict__ li) {
    int b = threadIdx.x;
    if (b >= Bv) return;
    int t = 0;
    for (int s = 0; s < Sv; s++) t += (ti[b * Sv + s] != 0);
    int a = 0;
    for (int s = 0; s < 4; s++) a += (ai[b * 4 + s] != 0);
    int l = 0;
    for (int s = 0; s < 64; s++) l += (li[b * 64 + s] != 0);
    d_tlen[b] = t;
    d_alen[b] = a;
    d_llen[b] = l;
}

// ---------------- embedding gather ----------------
__global__ void embed_kernel(const int* __restrict__ idx, const float* __restrict__ emb) {
    int i = blockIdx.x * 256 + threadIdx.x;
    if (i >= Bv * Sv * Ev) return;
    int e = i % Ev;
    int m = i / Ev;
    d_text[i] = emb[idx[m] * Ev + e];
}

// ---------------- tf32 MMA GEMM: 2-stage pipeline (R13 proven) ----------------
template <int EPI, bool BT, bool PW>
__global__ void __launch_bounds__(256, 3)
mma_gemm(const float* __restrict__ A, const float* __restrict__ Bm,
         const float* __restrict__ bias, float* __restrict__ C,
         int M, int N, int K) {
    __shared__ float As[2][16 * ASTR];
    __shared__ float Bs[2][16 * BSTR];

    const int m0 = blockIdx.y * 128;
    const int n0 = blockIdx.x * 64;
    const int tid = threadIdx.x;
    const int wid = tid >> 5;
    const int lane = tid & 31;
    const int grp = lane >> 2;
    const int tig = lane & 3;
    const int m_base = wid * 16;

    float c[8][4];
#pragma unroll
    for (int n = 0; n < 8; n++)
#pragma unroll
        for (int i = 0; i < 4; i++) c[n][i] = 0.f;

    const int a_m = tid >> 1;
    const int a_k4 = (tid & 1) * 4;
    float pwscale = 1.f;
    if (PW) pwscale = d_pwv[m0 + a_m];

    const int bt_nl = tid >> 2;
    const int bt_kk = (tid & 3) * 4;
    const int nb_kk = tid >> 4;
    const int nb_nl = (tid & 15) * 4;

    const int niter = ((K + 15) & ~15) >> 4;

    float4 ra0, ra1;
    float4 rbq;
    float rb4[4];

    auto loadG = [&](int it) {
        int k0 = it << 4;
        {
            int k = k0 + a_k4;
            ra0 = make_float4(0.f, 0.f, 0.f, 0.f);
            if (k < K) ra0 = *(const float4*)&A[(size_t)(m0 + a_m) * K + k];
            k = k0 + 8 + a_k4;
            ra1 = make_float4(0.f, 0.f, 0.f, 0.f);
            if (k < K) ra1 = *(const float4*)&A[(size_t)(m0 + a_m) * K + k];
            if (PW) {
                ra0.x *= pwscale; ra0.y *= pwscale; ra0.z *= pwscale; ra0.w *= pwscale;
                ra1.x *= pwscale; ra1.y *= pwscale; ra1.z *= pwscale; ra1.w *= pwscale;
            }
        }
        if (BT) {
            int row = n0 + bt_nl;
            int k = k0 + bt_kk;
            rbq = make_float4(0.f, 0.f, 0.f, 0.f);
            if (row < N && k < K) rbq = *(const float4*)&Bm[(size_t)row * K + k];
        } else {
            int k = k0 + nb_kk;
#pragma unroll
            for (int i = 0; i < 4; i++) {
                int n = n0 + nb_nl + i;
                rb4[i] = (k < K && n < N) ? Bm[(size_t)k * N + n] : 0.f;
            }
        }
    };
    auto storeS = [&](int buf) {
        As[buf][(a_k4 + 0) * ASTR + a_m] = to_tf32(ra0.x);
        As[buf][(a_k4 + 1) * ASTR + a_m] = to_tf32(ra0.y);
        As[buf][(a_k4 + 2) * ASTR + a_m] = to_tf32(ra0.z);
        As[buf][(a_k4 + 3) * ASTR + a_m] = to_tf32(ra0.w);
        As[buf][(8 + a_k4 + 0) * ASTR + a_m] = to_tf32(ra1.x);
        As[buf][(8 + a_k4 + 1) * ASTR + a_m] = to_tf32(ra1.y);
        As[buf][(8 + a_k4 + 2) * ASTR + a_m] = to_tf32(ra1.z);
        As[buf][(8 + a_k4 + 3) * ASTR + a_m] = to_tf32(ra1.w);
        if (BT) {
            Bs[buf][(bt_kk + 0) * BSTR + bt_nl] = to_tf32(rbq.x);
            Bs[buf][(bt_kk + 1) * BSTR + bt_nl] = to_tf32(rbq.y);
            Bs[buf][(bt_kk + 2) * BSTR + bt_nl] = to_tf32(rbq.z);
            Bs[buf][(bt_kk + 3) * BSTR + bt_nl] = to_tf32(rbq.w);
        } else {
#pragma unroll
            for (int i = 0; i < 4; i++)
                Bs[buf][nb_kk * BSTR + nb_nl + i] = to_tf32(rb4[i]);
        }
    };

    loadG(0);
    storeS(0);
    __syncthreads();

    for (int it = 0; it < niter; it++) {
        const int cur = it & 1;
        if (it + 1 < niter) loadG(it + 1);

#pragma unroll
        for (int ksub = 0; ksub < 2; ksub++) {
            const int kb = ksub * 8;
            uint32_t a0 = __float_as_uint(As[cur][(kb + tig) * ASTR + m_base + grp]);
            uint32_t a1 = __float_as_uint(As[cur][(kb + tig) * ASTR + m_base + grp + 8]);
            uint32_t a2 = __float_as_uint(As[cur][(kb + tig + 4) * ASTR + m_base + grp]);
            uint32_t a3 = __float_as_uint(As[cur][(kb + tig + 4) * ASTR + m_base + grp + 8]);
#pragma unroll
            for (int n = 0; n < 8; n++) {
                uint32_t b0 = __float_as_uint(Bs[cur][(kb + tig) * BSTR + n * 8 + grp]);
                uint32_t b1 = __float_as_uint(Bs[cur][(kb + tig + 4) * BSTR + n * 8 + grp]);
                asm volatile(
                    "mma.sync.aligned.m16n8k8.row.col.f32.tf32.tf32.f32 "
                    "{%0,%1,%2,%3}, {%4,%5,%6,%7}, {%8,%9}, {%0,%1,%2,%3};"
                    : "+f"(c[n][0]), "+f"(c[n][1]), "+f"(c[n][2]), "+f"(c[n][3])
                    : "r"(a0), "r"(a1), "r"(a2), "r"(a3), "r"(b0), "r"(b1));
            }
        }

        if (it + 1 < niter) storeS(1 - cur);
        __syncthreads();
    }

#pragma unroll
    for (int n = 0; n < 8; n++) {
        int col0 = n0 + n * 8 + 2 * tig;
#pragma unroll
        for (int half = 0; half < 2; half++) {
            int row = m0 + m_base + grp + half * 8;
            float v0 = c[n][half * 2 + 0];
            float v1 = c[n][half * 2 + 1];
            if (EPI == 0) {
                float b0 = bias ? bias[col0] : 0.f;
                float b1 = (bias && col0 + 1 < N) ? bias[col0 + 1] : 0.f;
                if (col0 < N) C[(size_t)row * N + col0] = v0 + b0;
                if (col0 + 1 < N) C[(size_t)row * N + col0 + 1] = v1 + b1;
            } else {
                int bb = row >> 8;
                int ss = row & 255;
                size_t base = (size_t)(ss * Bv + bb) * G4;
                if (col0 < N) C[base + col0] = v0 + bias[col0];
                if (col0 + 1 < N) C[base + col0 + 1] = v1 + bias[col0 + 1];
            }
        }
    }
}

// ---------------- persistent BiLSTM: 25 blocks/dir x 12 units, tf32 MMA ----------------
// 50 blocks, 768 thr = 24 warps. MMA: M=64 batches (4 m-tiles), N=48 rows (6 n-tiles).
// Row coding: jl = g*12 + u (gate g 0..3, unit u 0..11).
__global__ void __launch_bounds__(LSTM_THREADS, 1)
lstm_persist(const float* __restrict__ Wfh, const float* __restrict__ Wbh) {
    extern __shared__ float sm[];
    float* sH = sm + SH_OFF;   // [KP][SHSTR]
    float* sW = sm + SW_OFF;   // [KP][SWSTR] (48 rows used)
    float* sG = sm + SG_OFF;   // [48][64]
    float* sC = sm + SC_OFF;   // [12][64]

    const int d = blockIdx.x / LSTM_BLOCKS_PER_DIR;
    const int ub12 = (blockIdx.x % LSTM_BLOCKS_PER_DIR) * 12;
    const float* __restrict__ W = (d == 0) ? Wfh : Wbh;
    const int tid = threadIdx.x;
    const int wid = tid >> 5;
    const int lane = tid & 31;
    const int grp = lane >> 2;
    const int tig = lane & 3;

    // stage W (tf32), zero pads; zero sH pad rows
    for (int idx = tid; idx < KP * SWSTR; idx += LSTM_THREADS) {
        int k = idx / SWSTR, jl = idx % SWSTR;
        float v = 0.f;
        if (jl < NROWS && k < 300) {
            int g = jl / 12, u = jl % 12;
            v = to_tf32(W[(g * 300 + ub12 + u) * 300 + k]);
        }
        sW[k * SWSTR + jl] = v;
    }
    for (int idx = tid; idx < 4 * SHSTR; idx += LSTM_THREADS) sH[300 * SHSTR + idx] = 0.f;
    if (tid < 768) sC[tid] = 0.f;
    __syncthreads();

    const int uix = tid >> 6;       // unit 0..11
    const int b = tid & 63;
    int jrow[4];
#pragma unroll
    for (int g = 0; g < 4; g++) jrow[g] = g * 300 + ub12 + uix;
    const int u_l = uix;
    const int b_f = b;
    const unsigned nblk = (unsigned)LSTM_BLOCKS_PER_DIR;

    // mma warp tile coords
    const int m_b = (wid & 3) * 16;       // batch tile (wid&3: 0..3)
    const int n_b = (wid >> 2) * 8;       // gate-row tile (wid>>2: 0..5)

    float px0, px1, px2, px3;
    {
        const int t0 = (d == 0) ? 0 : (Sv - 1);
        const float* __restrict__ Xb =
            d_Xg + (size_t)(d * Sv + t0) * Bv * G4 + (size_t)b * G4;
        px0 = Xb[jrow[0]];
        px1 = Xb[jrow[1]];
        px2 = Xb[jrow[2]];
        px3 = Xb[jrow[3]];
    }

    for (int step = 0; step < Sv; step++) {
        const int t_x = (d == 0) ? step : (Sv - 1 - step);

        // 1. X preacts into sG (rows g*12 + uix)
        sG[(0 * 12 + uix) * 64 + b] = px0;
        sG[(1 * 12 + uix) * 64 + b] = px1;
        sG[(2 * 12 + uix) * 64 + b] = px2;
        sG[(3 * 12 + uix) * 64 + b] = px3;

        // 2. copy tf32 h_prev -> sH
        if (step > 0) {
            const int t_hp = (d == 0) ? (step - 1) : (Sv - step);
            const float4* __restrict__ Hp =
                (const float4*)(d_hseq2 + (size_t)(d * Sv + t_hp) * Hv * Bv);
            for (int i = tid; i < 4800; i += LSTM_THREADS) {
                int k = i >> 4;
                int b4 = (i & 15) * 4;
                *(float4*)&sH[k * SHSTR + b4] = Hp[i];
            }
        }
        __syncthreads();

        // 3. MMA: sG += h_prev @ W^T
        if (step > 0) {
            float c0 = 0.f, c1 = 0.f, c2 = 0.f, c3 = 0.f;
#pragma unroll 2
            for (int kb = 0; kb < KP; kb += 8) {
                uint32_t a0 = __float_as_uint(sH[(kb + tig) * SHSTR + m_b + grp]);
                uint32_t a1 = __float_as_uint(sH[(kb + tig) * SHSTR + m_b + grp + 8]);
                uint32_t a2 = __float_as_uint(sH[(kb + tig + 4) * SHSTR + m_b + grp]);
                uint32_t a3 = __float_as_uint(sH[(kb + tig + 4) * SHSTR + m_b + grp + 8]);
                uint32_t bb0 = __float_as_uint(sW[(kb + tig) * SWSTR + n_b + grp]);
                uint32_t bb1 = __float_as_uint(sW[(kb + tig + 4) * SWSTR + n_b + grp]);
                asm volatile(
                    "mma.sync.aligned.m16n8k8.row.col.f32.tf32.tf32.f32 "
                    "{%0,%1,%2,%3}, {%4,%5,%6,%7}, {%8,%9}, {%0,%1,%2,%3};"
                    : "+f"(c0), "+f"(c1), "+f"(c2), "+f"(c3)
                    : "r"(a0), "r"(a1), "r"(a2), "r"(a3), "r"(bb0), "r"(bb1));
            }
            int nn = n_b + 2 * tig;
            sG[nn * 64 + m_b + grp] += c0;
            sG[(nn + 1) * 64 + m_b + grp] += c1;
            sG[nn * 64 + m_b + grp + 8] += c2;
            sG[(nn + 1) * 64 + m_b + grp + 8] += c3;
        }
        __syncthreads();

        // 4. finalize: 12 units x 64 batches
        {
            float gi = sG[(0 * 12 + u_l) * 64 + b_f];
            float gf = sG[(1 * 12 + u_l) * 64 + b_f];
            float gg = sG[(2 * 12 + u_l) * 64 + b_f];
            float go = sG[(3 * 12 + u_l) * 64 + b_f];
            float cp = sC[u_l * 64 + b_f];
            float si = 1.f / (1.f + expf(-gi));
            float sf = 1.f / (1.f + expf(-gf));
            float so = 1.f / (1.f + expf(-go));
            float cc = sf * cp + si * tanhf(gg);
            sC[u_l * 64 + b_f] = cc;
            float h = so * tanhf(cc);
            size_t off = ((size_t)(d * Sv + t_x) * Hv + ub12 + u_l) * 64 + b_f;
            d_hseq[off] = h;
            d_hseq2[off] = to_tf32(h);
        }

        // 5. prefetch next X
        if (step + 1 < Sv) {
            const int tn = (d == 0) ? (step + 1) : (Sv - 2 - step);
            const float* __restrict__ Xn =
                d_Xg + (size_t)(d * Sv + tn) * Bv * G4 + (size_t)b * G4;
            px0 = Xn[jrow[0]];
            px1 = Xn[jrow[1]];
            px2 = Xn[jrow[2]];
            px3 = Xn[jrow[3]];
        }

        // 6. grid barrier (tid0-only arrive+poll)
        __syncthreads();
        if (tid == 0) {
            __threadfence();
            atomicAdd(&d_barr[d * Sv + step], 1u);
            const unsigned* ctr = &d_barr[d * Sv + step];
            while (ld_acquire(ctr) < nblk) {}
        }
        __syncthreads();
    }
}

// ---------------- assemble text_out ----------------
__global__ void assemble_to() {
    int i = blockIdx.x * 256 + threadIdx.x;
    if (i >= Bv * Sv * H2) return;
    int h = i % H2;
    int bs = i / H2;
    int s = bs % Sv;
    int b = bs / Sv;
    int dsel = (h >= Hv) ? 1 : 0;
    int u = h - dsel * Hv;
    d_to[i] = d_hseq[((size_t)(dsel * Sv + s) * Hv + u) * 64 + b];
}

// ---------------- V = bil_W @ rel_embed^T ----------------
__global__ void vprep(const float* __restrict__ bw, const float* __restrict__ re) {
    int r = blockIdx.x;
    for (int i = threadIdx.x; i < G4; i += 256) {
        float a = 0.f;
#pragma unroll
        for (int jj = 0; jj < RELDv; jj++) a += bw[i * RELDv + jj] * re[r * RELDv + jj];
        d_V[r * G4 + i] = a;
    }
}

// ---------------- relation scores ----------------
__global__ void relscore(const int* __restrict__ head, const int* __restrict__ behead,
                         const int* __restrict__ rel, const float* __restrict__ bilb) {
    int g = blockIdx.x * 8 + (threadIdx.x >> 5);
    int lane = threadIdx.x & 31;
    if (g >= Bv * Rv) return;
    int b = g / Rv;
    int rr = rel[g];
    float dotv = 0.f;
    if (rr != 0) {
        int h1 = head[g], h2 = behead[g];
        const float* __restrict__ n1 = d_to + (size_t)(b * Sv + h1) * H2;
        const float* __restrict__ n2 = d_to + (size_t)(b * Sv + h2) * H2;
        const float* __restrict__ V = d_V + rr * G4;
        for (int i = lane; i < H2; i += 32) dotv += n1[i] * V[i] + n2[i] * V[H2 + i];
    }
#pragma unroll
    for (int o = 16; o; o >>= 1) dotv += __shfl_down_sync(0xffffffffu, dotv, o);
    if (lane == 0) d_score[g] = 1.f / (1.f + expf(-(dotv + bilb[0])));
}

// ---------------- position weights ----------------
__global__ void pwv_kernel() {
    int b = blockIdx.x;
    int s = threadIdx.x;
    float tl = (float)d_tlen[b];
    float al = (float)d_alen[b];
    float l0 = (float)d_llen[b];
    float l1 = l0 + al - 1.f;
    float ctx = tl - al;
    float jf = (float)s;
    float w;
    if (jf < l0) w = 1.f - (l0 - jf) / ctx;
    else if (jf <= l1) w = 0.f;
    else if (jf < tl) w = 1.f - (jf - l1) / ctx;
    else w = 0.f;
    d_pwv[b * Sv + s] = w;
}

// ---------------- sparse GCN apply ----------------
__global__ void gcn_apply(const int* __restrict__ head, const int* __restrict__ behead,
                          const float* __restrict__ bias, float* __restrict__ out) {
    int bs = blockIdx.x;
    int b = bs >> 8;
    int s1 = bs & 255;
    const int* hd = head + b * Rv;
    int L = 0, Rr = Rv;
    while (L < Rr) { int m = (L + Rr) >> 1; if (hd[m] < s1) L = m + 1; else Rr = m; }
    int lo = L;
    Rr = Rv;
    while (L < Rr) { int m = (L + Rr) >> 1; if (hd[m] <= s1) L = m + 1; else Rr = m; }
    int hi = L;
    float den = 1.f;
    for (int r = lo; r < hi; r++) den += d_score[b * Rv + r];
    float inv = 1.f / den;
    for (int h = threadIdx.x; h < H2; h += 128) {
        float a = 0.f;
        for (int r = lo; r < hi; r++)
            a += d_score[b * Rv + r] * d_hid[(size_t)(b * Sv + behead[b * Rv + r]) * H2 + h];
        float v = a * inv + bias[h];
        out[(size_t)(b * Sv + s1) * H2 + h] = fmaxf(v, 0.f);
    }
}

// ---------------- attention ----------------
__global__ void xsum_kernel(const float* __restrict__ x) {
    int b = blockIdx.x;
    int h = threadIdx.x;
    if (h >= H2) return;
    int l0 = d_llen[b];
    int l1 = l0 + d_alen[b] - 1;
    if (l1 > Sv - 1) l1 = Sv - 1;
    float a = 0.f;
    for (int s = l0; s <= l1; s++) a += x[(size_t)(b * Sv + s) * H2 + h];
    d_xsum[b * H2 + h] = a;
}

__global__ void attscore() {
    int g = blockIdx.x * 8 + (threadIdx.x >> 5);
    int lane = threadIdx.x & 31;
    if (g >= Bv * Sv) return;
    int b = g >> 8;
    float a = 0.f;
    for (int i = lane; i < H2; i += 32) a += d_xsum[b * H2 + i] * d_to[(size_t)g * H2 + i];
#pragma unroll
    for (int o = 16; o; o >>= 1) a += __shfl_down_sync(0xffffffffu, a, o);
    if (lane == 0) d_attsc[g] = a;
}

__global__ void softmax_kernel() {
    __shared__ float red[256];
    int b = blockIdx.x;
    int tid = threadIdx.x;
    float v = d_attsc[b * Sv + tid];
    red[tid] = v;
    __syncthreads();
    for (int o = 128; o; o >>= 1) {
        if (tid < o) red[tid] = fmaxf(red[tid], red[tid + o]);
        __syncthreads();
    }
    float smax = red[0];
    __syncthreads();
    float e = expf(v - smax);
    red[tid] = e;
    __syncthreads();
    for (int o = 128; o; o >>= 1) {
        if (tid < o) red[tid] += red[tid + o];
        __syncthreads();
    }
    d_alpha[b * Sv + tid] = e / red[0];
}

__global__ void outvec_kernel() {
    int b = blockIdx.x;
    int h = threadIdx.x;
    if (h >= H2) return;
    float a = 0.f;
    for (int s = 0; s < Sv; s++) a += d_alpha[b * Sv + s] * d_to[(size_t)(b * Sv + s) * H2 + h];
    d_ov[b * H2 + h] = a;
}

__global__ void final_fc(const float* __restrict__ fcW, const float* __restrict__ fcb,
                         float* __restrict__ out) {
    int b = blockIdx.x;
    int p = threadIdx.x >> 5;
    int lane = threadIdx.x & 31;
    if (p >= 3) return;
    float a = 0.f;
    for (int h = lane; h < H2; h += 32) a += d_ov[b * H2 + h] * fcW[h * 3 + p];
#pragma unroll
    for (int o = 16; o; o >>= 1) a += __shfl_down_sync(0xffffffffu, a, o);
    if (lane == 0) out[b * 3 + p] = a + fcb[p];
}

// ---------------- launch ----------------
extern "C" void kernel_launch(void* const* d_in, const int* in_sizes, int n_in,
                              void* d_out, int out_size) {
    const int* text_indices = (const int*)d_in[0];
    const int* aspect_indices = (const int*)d_in[1];
    const int* left_indices = (const int*)d_in[2];
    const int* head_vector = (const int*)d_in[4];
    const int* behead_vector = (const int*)d_in[5];
    const int* relation_vector = (const int*)d_in[6];
    const float* embed_table = (const float*)d_in[7];
    const float* rel_embed = (const float*)d_in[8];
    const float* Wf_ih = (const float*)d_in[9];
    const float* Wf_hh = (const float*)d_in[10];
    const float* bf = (const float*)d_in[11];
    const float* Wb_ih = (const float*)d_in[12];
    const float* Wb_hh = (const float*)d_in[13];
    const float* bb = (const float*)d_in[14];
    const float* bil_W = (const float*)d_in[15];
    const float* bil_b = (const float*)d_in[16];
    const float* gc1_W = (const float*)d_in[17];
    const float* gc1_b = (const float*)d_in[18];
    const float* gc2_W = (const float*)d_in[19];
    const float* gc2_b = (const float*)d_in[20];
    const float* fc_W = (const float*)d_in[21];
    const float* fc_b = (const float*)d_in[22];
    float* out = (float*)d_out;

    float* p_text;  cudaGetSymbolAddress((void**)&p_text, d_text);
    float* p_Xg;    cudaGetSymbolAddress((void**)&p_Xg, d_Xg);
    float* p_to;    cudaGetSymbolAddress((void**)&p_to, d_to);
    float* p_hid;   cudaGetSymbolAddress((void**)&p_hid, d_hid);
    float* p_x1;    cudaGetSymbolAddress((void**)&p_x1, d_x1);

    cudaFuncSetAttribute(lstm_persist, cudaFuncAttributeMaxDynamicSharedMemorySize,
                         LSTM_SMEM_BYTES);

    len_kernel<<<1, 64>>>(text_indices, aspect_indices, left_indices);
    embed_kernel<<<(Bv * Sv * Ev + 255) / 256, 256>>>(text_indices, embed_table);

    {
        dim3 g((G4 + 63) / 64, (Bv * Sv) / 128);
        mma_gemm<1, true, false><<<g, 256>>>(p_text, Wf_ih, bf, p_Xg, Bv * Sv, G4, Ev);
        mma_gemm<1, true, false><<<g, 256>>>(p_text, Wb_ih, bb,
                                             p_Xg + (size_t)Sv * Bv * G4, Bv * Sv, G4, Ev);
    }

    barr_reset<<<1, 512>>>();
    lstm_persist<<<2 * LSTM_BLOCKS_PER_DIR, LSTM_THREADS, LSTM_SMEM_BYTES>>>(Wf_hh, Wb_hh);

    assemble_to<<<(Bv * Sv * H2 + 255) / 256, 256>>>();

    vprep<<<NRELv, 256>>>(bil_W, rel_embed);
    relscore<<<(Bv * Rv) / 8, 256>>>(head_vector, behead_vector, relation_vector, bil_b);

    pwv_kernel<<<Bv, Sv>>>();

    {
        dim3 g((H2 + 63) / 64, (Bv * Sv) / 128);
        mma_gemm<0, false, true><<<g, 256>>>(p_to, gc1_W, nullptr, p_hid, Bv * Sv, H2, H2);
    }
    gcn_apply<<<Bv * Sv, 128>>>(head_vector, behead_vector, gc1_b, p_x1);

    {
        dim3 g((H2 + 63) / 64, (Bv * Sv) / 128);
        mma_gemm<0, false, true><<<g, 256>>>(p_x1, gc2_W, nullptr, p_hid, Bv * Sv, H2, H2);
    }
    gcn_apply<<<Bv * Sv, 128>>>(head_vector, behead_vector, gc2_b, p_x1);

    xsum_kernel<<<Bv, 640>>>(p_x1);
    attscore<<<(Bv * Sv) / 8, 256>>>();
    softmax_kernel<<<Bv, 256>>>();
    outvec_kernel<<<Bv, 640>>>();
    final_fc<<<Bv, 96>>>(fc_W, fc_b, out);

    (void)in_sizes; (void)n_in; (void)out_size;
}

// round 17
// speedup vs baseline: 1.3035x; 1.3035x over previous
#include <cuda_runtime.h>
#include <stdint.h>
#include <math.h>

#define Bv 64
#define Sv 256
#define Ev 300
#define Hv 300
#define H2 600
#define G4 1200
#define Rv 512
#define NRELv 46
#define RELDv 50

#define LSTM_BLOCKS_PER_DIR 75   // 4 units (16 gate rows) per block
#define LSTM_THREADS 256

// lstm smem (floats)
#define KP 304
#define SHSTR 72
#define SWSTR 24
#define SH_OFF 0                              // sH [KP][72]
#define SW_OFF (KP * SHSTR)                   // sW [KP][24]
#define SG_OFF (SW_OFF + KP * SWSTR)          // sG [16][64]
#define SC_OFF (SG_OFF + 1024)                // sC [4][64]
#define LSTM_SMEM_BYTES ((SC_OFF + 256) * 4)

// mma gemm tile config
#define ASTR 136
#define BSTR 72

// ---------------- device scratch ----------------
__device__ float d_text[Bv * Sv * Ev];
__device__ float d_Xg[2 * Sv * Bv * G4];
__device__ float d_hseq[2 * Sv * Hv * Bv];    // fp32 h (for text_out)
__device__ float d_hseq2[2 * Sv * Hv * Bv];   // tf32-rounded h (for recurrence MMA)
__device__ float d_to[Bv * Sv * H2];
__device__ float d_hid[Bv * Sv * H2];
__device__ float d_x1[Bv * Sv * H2];
__device__ float d_V[NRELv * G4];
__device__ float d_score[Bv * Rv];
__device__ float d_pwv[Bv * Sv];
__device__ float d_xsum[Bv * H2];
__device__ float d_attsc[Bv * Sv];
__device__ float d_alpha[Bv * Sv];
__device__ float d_ov[Bv * H2];
__device__ int d_tlen[Bv], d_alen[Bv], d_llen[Bv];
__device__ unsigned d_barr[2 * Sv];

__device__ __forceinline__ unsigned ld_acquire(const unsigned* p) {
    unsigned v;
    asm volatile("ld.acquire.gpu.global.u32 %0, [%1];" : "=r"(v) : "l"(p) : "memory");
    return v;
}

__device__ __forceinline__ void atom_add_release(unsigned* p) {
    unsigned old;
    asm volatile("atom.release.gpu.global.add.u32 %0, [%1], 1;"
                 : "=r"(old) : "l"(p) : "memory");
}

__device__ __forceinline__ float to_tf32(float x) {
    uint32_t r;
    asm("cvt.rna.tf32.f32 %0, %1;" : "=r"(r) : "f"(x));
    return __uint_as_float(r);
}

// ---------------- barrier reset ----------------
__global__ void barr_reset() {
    int i = threadIdx.x;
    if (i < 2 * Sv) d_barr[i] = 0u;
}

// ---------------- lengths ----------------
__global__ void len_kernel(const int* __restrict__ ti, const int* __restrict__ ai,
                           const int* __restrict__ li) {
    int b = threadIdx.x;
    if (b >= Bv) return;
    int t = 0;
    for (int s = 0; s < Sv; s++) t += (ti[b * Sv + s] != 0);
    int a = 0;
    for (int s = 0; s < 4; s++) a += (ai[b * 4 + s] != 0);
    int l = 0;
    for (int s = 0; s < 64; s++) l += (li[b * 64 + s] != 0);
    d_tlen[b] = t;
    d_alen[b] = a;
    d_llen[b] = l;
}

// ---------------- embedding gather ----------------
__global__ void embed_kernel(const int* __restrict__ idx, const float* __restrict__ emb) {
    int i = blockIdx.x * 256 + threadIdx.x;
    if (i >= Bv * Sv * Ev) return;
    int e = i % Ev;
    int m = i / Ev;
    d_text[i] = emb[idx[m] * Ev + e];
}

// ---------------- tf32 MMA GEMM: 2-stage pipeline (R13 proven) ----------------
template <int EPI, bool BT, bool PW>
__global__ void __launch_bounds__(256, 3)
mma_gemm(const float* __restrict__ A, const float* __restrict__ Bm,
         const float* __restrict__ bias, float* __restrict__ C,
         int M, int N, int K) {
    __shared__ float As[2][16 * ASTR];
    __shared__ float Bs[2][16 * BSTR];

    const int m0 = blockIdx.y * 128;
    const int n0 = blockIdx.x * 64;
    const int tid = threadIdx.x;
    const int wid = tid >> 5;
    const int lane = tid & 31;
    const int grp = lane >> 2;
    const int tig = lane & 3;
    const int m_base = wid * 16;

    float c[8][4];
#pragma unroll
    for (int n = 0; n < 8; n++)
#pragma unroll
        for (int i = 0; i < 4; i++) c[n][i] = 0.f;

    const int a_m = tid >> 1;
    const int a_k4 = (tid & 1) * 4;
    float pwscale = 1.f;
    if (PW) pwscale = d_pwv[m0 + a_m];

    const int bt_nl = tid >> 2;
    const int bt_kk = (tid & 3) * 4;
    const int nb_kk = tid >> 4;
    const int nb_nl = (tid & 15) * 4;

    const int niter = ((K + 15) & ~15) >> 4;

    float4 ra0, ra1;
    float4 rbq;
    float rb4[4];

    auto loadG = [&](int it) {
        int k0 = it << 4;
        {
            int k = k0 + a_k4;
            ra0 = make_float4(0.f, 0.f, 0.f, 0.f);
            if (k < K) ra0 = *(const float4*)&A[(size_t)(m0 + a_m) * K + k];
            k = k0 + 8 + a_k4;
            ra1 = make_float4(0.f, 0.f, 0.f, 0.f);
            if (k < K) ra1 = *(const float4*)&A[(size_t)(m0 + a_m) * K + k];
            if (PW) {
                ra0.x *= pwscale; ra0.y *= pwscale; ra0.z *= pwscale; ra0.w *= pwscale;
                ra1.x *= pwscale; ra1.y *= pwscale; ra1.z *= pwscale; ra1.w *= pwscale;
            }
        }
        if (BT) {
            int row = n0 + bt_nl;
            int k = k0 + bt_kk;
            rbq = make_float4(0.f, 0.f, 0.f, 0.f);
            if (row < N && k < K) rbq = *(const float4*)&Bm[(size_t)row * K + k];
        } else {
            int k = k0 + nb_kk;
#pragma unroll
            for (int i = 0; i < 4; i++) {
                int n = n0 + nb_nl + i;
                rb4[i] = (k < K && n < N) ? Bm[(size_t)k * N + n] : 0.f;
            }
        }
    };
    auto storeS = [&](int buf) {
        As[buf][(a_k4 + 0) * ASTR + a_m] = to_tf32(ra0.x);
        As[buf][(a_k4 + 1) * ASTR + a_m] = to_tf32(ra0.y);
        As[buf][(a_k4 + 2) * ASTR + a_m] = to_tf32(ra0.z);
        As[buf][(a_k4 + 3) * ASTR + a_m] = to_tf32(ra0.w);
        As[buf][(8 + a_k4 + 0) * ASTR + a_m] = to_tf32(ra1.x);
        As[buf][(8 + a_k4 + 1) * ASTR + a_m] = to_tf32(ra1.y);
        As[buf][(8 + a_k4 + 2) * ASTR + a_m] = to_tf32(ra1.z);
        As[buf][(8 + a_k4 + 3) * ASTR + a_m] = to_tf32(ra1.w);
        if (BT) {
            Bs[buf][(bt_kk + 0) * BSTR + bt_nl] = to_tf32(rbq.x);
            Bs[buf][(bt_kk + 1) * BSTR + bt_nl] = to_tf32(rbq.y);
            Bs[buf][(bt_kk + 2) * BSTR + bt_nl] = to_tf32(rbq.z);
            Bs[buf][(bt_kk + 3) * BSTR + bt_nl] = to_tf32(rbq.w);
        } else {
#pragma unroll
            for (int i = 0; i < 4; i++)
                Bs[buf][nb_kk * BSTR + nb_nl + i] = to_tf32(rb4[i]);
        }
    };

    loadG(0);
    storeS(0);
    __syncthreads();

    for (int it = 0; it < niter; it++) {
        const int cur = it & 1;
        if (it + 1 < niter) loadG(it + 1);

#pragma unroll
        for (int ksub = 0; ksub < 2; ksub++) {
            const int kb = ksub * 8;
            uint32_t a0 = __float_as_uint(As[cur][(kb + tig) * ASTR + m_base + grp]);
            uint32_t a1 = __float_as_uint(As[cur][(kb + tig) * ASTR + m_base + grp + 8]);
            uint32_t a2 = __float_as_uint(As[cur][(kb + tig + 4) * ASTR + m_base + grp]);
            uint32_t a3 = __float_as_uint(As[cur][(kb + tig + 4) * ASTR + m_base + grp + 8]);
#pragma unroll
            for (int n = 0; n < 8; n++) {
                uint32_t b0 = __float_as_uint(Bs[cur][(kb + tig) * BSTR + n * 8 + grp]);
                uint32_t b1 = __float_as_uint(Bs[cur][(kb + tig + 4) * BSTR + n * 8 + grp]);
                asm volatile(
                    "mma.sync.aligned.m16n8k8.row.col.f32.tf32.tf32.f32 "
                    "{%0,%1,%2,%3}, {%4,%5,%6,%7}, {%8,%9}, {%0,%1,%2,%3};"
                    : "+f"(c[n][0]), "+f"(c[n][1]), "+f"(c[n][2]), "+f"(c[n][3])
                    : "r"(a0), "r"(a1), "r"(a2), "r"(a3), "r"(b0), "r"(b1));
            }
        }

        if (it + 1 < niter) storeS(1 - cur);
        __syncthreads();
    }

#pragma unroll
    for (int n = 0; n < 8; n++) {
        int col0 = n0 + n * 8 + 2 * tig;
#pragma unroll
        for (int half = 0; half < 2; half++) {
            int row = m0 + m_base + grp + half * 8;
            float v0 = c[n][half * 2 + 0];
            float v1 = c[n][half * 2 + 1];
            if (EPI == 0) {
                float b0 = bias ? bias[col0] : 0.f;
                float b1 = (bias && col0 + 1 < N) ? bias[col0 + 1] : 0.f;
                if (col0 < N) C[(size_t)row * N + col0] = v0 + b0;
                if (col0 + 1 < N) C[(size_t)row * N + col0 + 1] = v1 + b1;
            } else {
                int bb = row >> 8;
                int ss = row & 255;
                size_t base = (size_t)(ss * Bv + bb) * G4;
                if (col0 < N) C[base + col0] = v0 + bias[col0];
                if (col0 + 1 < N) C[base + col0 + 1] = v1 + bias[col0 + 1];
            }
        }
    }
}

// ---------------- persistent BiLSTM: R14 structure, early-release barrier ----------------
__global__ void __launch_bounds__(LSTM_THREADS, 1)
lstm_persist(const float* __restrict__ Wfh, const float* __restrict__ Wbh) {
    extern __shared__ float sm[];
    float* sH = sm + SH_OFF;   // [KP][SHSTR]
    float* sW = sm + SW_OFF;   // [KP][SWSTR] (16 rows used)
    float* sG = sm + SG_OFF;   // [16][64]
    float* sC = sm + SC_OFF;   // [4][64]

    const int d = blockIdx.x / LSTM_BLOCKS_PER_DIR;
    const int ub4 = (blockIdx.x % LSTM_BLOCKS_PER_DIR) * 4;
    const float* __restrict__ W = (d == 0) ? Wfh : Wbh;
    const int tid = threadIdx.x;
    const int wid = tid >> 5;
    const int lane = tid & 31;
    const int grp = lane >> 2;
    const int tig = lane & 3;

    // stage W (tf32), zero pads; zero sH pad rows
    for (int idx = tid; idx < KP * SWSTR; idx += LSTM_THREADS) {
        int k = idx / SWSTR, jl = idx % SWSTR;
        float v = 0.f;
        if (jl < 16 && k < 300) {
            int g = jl >> 2, u = jl & 3;
            v = to_tf32(W[(g * 300 + ub4 + u) * 300 + k]);
        }
        sW[k * SWSTR + jl] = v;
    }
    for (int idx = tid; idx < 4 * SHSTR; idx += LSTM_THREADS) sH[300 * SHSTR + idx] = 0.f;
    sC[tid] = 0.f;
    __syncthreads();

    const int jg = tid >> 6;
    const int b = tid & 63;
    int jrow[4];
#pragma unroll
    for (int u = 0; u < 4; u++) jrow[u] = jg * 300 + ub4 + u;
    const int u_l = tid >> 6;
    const int b_f = tid & 63;
    const unsigned nblk = (unsigned)LSTM_BLOCKS_PER_DIR;

    const int m_b = (wid & 3) * 16;
    const int n_b = (wid >> 2) * 8;

    float px0, px1, px2, px3;
    {
        const int t0 = (d == 0) ? 0 : (Sv - 1);
        const float* __restrict__ Xb =
            d_Xg + (size_t)(d * Sv + t0) * Bv * G4 + (size_t)b * G4;
        px0 = Xb[jrow[0]];
        px1 = Xb[jrow[1]];
        px2 = Xb[jrow[2]];
        px3 = Xb[jrow[3]];
    }

    for (int step = 0; step < Sv; step++) {
        const int t_x = (d == 0) ? step : (Sv - 1 - step);

        // 1. X preacts into sG
        sG[(jg * 4 + 0) * 64 + b] = px0;
        sG[(jg * 4 + 1) * 64 + b] = px1;
        sG[(jg * 4 + 2) * 64 + b] = px2;
        sG[(jg * 4 + 3) * 64 + b] = px3;

        // 2. copy tf32 h_prev -> sH
        if (step > 0) {
            const int t_hp = (d == 0) ? (step - 1) : (Sv - step);
            const float4* __restrict__ Hp =
                (const float4*)(d_hseq2 + (size_t)(d * Sv + t_hp) * Hv * Bv);
            for (int i = tid; i < 4800; i += LSTM_THREADS) {
                int k = i >> 4;
                int b4 = (i & 15) * 4;
                *(float4*)&sH[k * SHSTR + b4] = Hp[i];
            }
        }
        __syncthreads();

        // 3. MMA: sG += h_prev @ W^T
        if (step > 0) {
            float c0 = 0.f, c1 = 0.f, c2 = 0.f, c3 = 0.f;
#pragma unroll 2
            for (int kb = 0; kb < KP; kb += 8) {
                uint32_t a0 = __float_as_uint(sH[(kb + tig) * SHSTR + m_b + grp]);
                uint32_t a1 = __float_as_uint(sH[(kb + tig) * SHSTR + m_b + grp + 8]);
                uint32_t a2 = __float_as_uint(sH[(kb + tig + 4) * SHSTR + m_b + grp]);
                uint32_t a3 = __float_as_uint(sH[(kb + tig + 4) * SHSTR + m_b + grp + 8]);
                uint32_t bb0 = __float_as_uint(sW[(kb + tig) * SWSTR + n_b + grp]);
                uint32_t bb1 = __float_as_uint(sW[(kb + tig + 4) * SWSTR + n_b + grp]);
                asm volatile(
                    "mma.sync.aligned.m16n8k8.row.col.f32.tf32.tf32.f32 "
                    "{%0,%1,%2,%3}, {%4,%5,%6,%7}, {%8,%9}, {%0,%1,%2,%3};"
                    : "+f"(c0), "+f"(c1), "+f"(c2), "+f"(c3)
                    : "r"(a0), "r"(a1), "r"(a2), "r"(a3), "r"(bb0), "r"(bb1));
            }
            int nn = n_b + 2 * tig;
            sG[nn * 64 + m_b + grp] += c0;
            sG[(nn + 1) * 64 + m_b + grp] += c1;
            sG[nn * 64 + m_b + grp + 8] += c2;
            sG[(nn + 1) * 64 + m_b + grp + 8] += c3;
        }
        __syncthreads();

        // 4. finalize: 4 units x 64 batches; write fp32 h + tf32 h
        {
            float gi = sG[(0 * 4 + u_l) * 64 + b_f];
            float gf = sG[(1 * 4 + u_l) * 64 + b_f];
            float gg = sG[(2 * 4 + u_l) * 64 + b_f];
            float go = sG[(3 * 4 + u_l) * 64 + b_f];
            float cp = sC[u_l * 64 + b_f];
            float si = 1.f / (1.f + expf(-gi));
            float sf = 1.f / (1.f + expf(-gf));
            float so = 1.f / (1.f + expf(-go));
            float cc = sf * cp + si * tanhf(gg);
            sC[u_l * 64 + b_f] = cc;
            float h = so * tanhf(cc);
            size_t off = ((size_t)(d * Sv + t_x) * Hv + ub4 + u_l) * 64 + b_f;
            d_hseq[off] = h;
            d_hseq2[off] = to_tf32(h);
        }

        // 5. early arrive: release-atomic right after h stores are block-ordered.
        //    (syncthreads + atom.release establishes happens-before for all the
        //     block's h stores; consumer does ld.acquire.)
        __syncthreads();
        if (tid == 0) atom_add_release(&d_barr[d * Sv + step]);

        // 6. prefetch next X under the barrier wait
        if (step + 1 < Sv) {
            const int tn = (d == 0) ? (step + 1) : (Sv - 2 - step);
            const float* __restrict__ Xn =
                d_Xg + (size_t)(d * Sv + tn) * Bv * G4 + (size_t)b * G4;
            px0 = Xn[jrow[0]];
            px1 = Xn[jrow[1]];
            px2 = Xn[jrow[2]];
            px3 = Xn[jrow[3]];
        }

        // 7. wait (tid0 only), then block-wide release
        if (tid == 0) {
            const unsigned* ctr = &d_barr[d * Sv + step];
            while (ld_acquire(ctr) < nblk) {}
        }
        __syncthreads();
    }
}

// ---------------- assemble text_out ----------------
__global__ void assemble_to() {
    int i = blockIdx.x * 256 + threadIdx.x;
    if (i >= Bv * Sv * H2) return;
    int h = i % H2;
    int bs = i / H2;
    int s = bs % Sv;
    int b = bs / Sv;
    int dsel = (h >= Hv) ? 1 : 0;
    int u = h - dsel * Hv;
    d_to[i] = d_hseq[((size_t)(dsel * Sv + s) * Hv + u) * 64 + b];
}

// ---------------- V = bil_W @ rel_embed^T ----------------
__global__ void vprep(const float* __restrict__ bw, const float* __restrict__ re) {
    int r = blockIdx.x;
    for (int i = threadIdx.x; i < G4; i += 256) {
        float a = 0.f;
#pragma unroll
        for (int jj = 0; jj < RELDv; jj++) a += bw[i * RELDv + jj] * re[r * RELDv + jj];
        d_V[r * G4 + i] = a;
    }
}

// ---------------- relation scores ----------------
__global__ void relscore(const int* __restrict__ head, const int* __restrict__ behead,
                         const int* __restrict__ rel, const float* __restrict__ bilb) {
    int g = blockIdx.x * 8 + (threadIdx.x >> 5);
    int lane = threadIdx.x & 31;
    if (g >= Bv * Rv) return;
    int b = g / Rv;
    int rr = rel[g];
    float dotv = 0.f;
    if (rr != 0) {
        int h1 = head[g], h2 = behead[g];
        const float* __restrict__ n1 = d_to + (size_t)(b * Sv + h1) * H2;
        const float* __restrict__ n2 = d_to + (size_t)(b * Sv + h2) * H2;
        const float* __restrict__ V = d_V + rr * G4;
        for (int i = lane; i < H2; i += 32) dotv += n1[i] * V[i] + n2[i] * V[H2 + i];
    }
#pragma unroll
    for (int o = 16; o; o >>= 1) dotv += __shfl_down_sync(0xffffffffu, dotv, o);
    if (lane == 0) d_score[g] = 1.f / (1.f + expf(-(dotv + bilb[0])));
}

// ---------------- position weights ----------------
__global__ void pwv_kernel() {
    int b = blockIdx.x;
    int s = threadIdx.x;
    float tl = (float)d_tlen[b];
    float al = (float)d_alen[b];
    float l0 = (float)d_llen[b];
    float l1 = l0 + al - 1.f;
    float ctx = tl - al;
    float jf = (float)s;
    float w;
    if (jf < l0) w = 1.f - (l0 - jf) / ctx;
    else if (jf <= l1) w = 0.f;
    else if (jf < tl) w = 1.f - (jf - l1) / ctx;
    else w = 0.f;
    d_pwv[b * Sv + s] = w;
}

// ---------------- sparse GCN apply ----------------
__global__ void gcn_apply(const int* __restrict__ head, const int* __restrict__ behead,
                          const float* __restrict__ bias, float* __restrict__ out) {
    int bs = blockIdx.x;
    int b = bs >> 8;
    int s1 = bs & 255;
    const int* hd = head + b * Rv;
    int L = 0, Rr = Rv;
    while (L < Rr) { int m = (L + Rr) >> 1; if (hd[m] < s1) L = m + 1; else Rr = m; }
    int lo = L;
    Rr = Rv;
    while (L < Rr) { int m = (L + Rr) >> 1; if (hd[m] <= s1) L = m + 1; else Rr = m; }
    int hi = L;
    float den = 1.f;
    for (int r = lo; r < hi; r++) den += d_score[b * Rv + r];
    float inv = 1.f / den;
    for (int h = threadIdx.x; h < H2; h += 128) {
        float a = 0.f;
        for (int r = lo; r < hi; r++)
            a += d_score[b * Rv + r] * d_hid[(size_t)(b * Sv + behead[b * Rv + r]) * H2 + h];
        float v = a * inv + bias[h];
        out[(size_t)(b * Sv + s1) * H2 + h] = fmaxf(v, 0.f);
    }
}

// ---------------- attention ----------------
__global__ void xsum_kernel(const float* __restrict__ x) {
    int b = blockIdx.x;
    int h = threadIdx.x;
    if (h >= H2) return;
    int l0 = d_llen[b];
    int l1 = l0 + d_alen[b] - 1;
    if (l1 > Sv - 1) l1 = Sv - 1;
    float a = 0.f;
    for (int s = l0; s <= l1; s++) a += x[(size_t)(b * Sv + s) * H2 + h];
    d_xsum[b * H2 + h] = a;
}

__global__ void attscore() {
    int g = blockIdx.x * 8 + (threadIdx.x >> 5);
    int lane = threadIdx.x & 31;
    if (g >= Bv * Sv) return;
    int b = g >> 8;
    float a = 0.f;
    for (int i = lane; i < H2; i += 32) a += d_xsum[b * H2 + i] * d_to[(size_t)g * H2 + i];
#pragma unroll
    for (int o = 16; o; o >>= 1) a += __shfl_down_sync(0xffffffffu, a, o);
    if (lane == 0) d_attsc[g] = a;
}

__global__ void softmax_kernel() {
    __shared__ float red[256];
    int b = blockIdx.x;
    int tid = threadIdx.x;
    float v = d_attsc[b * Sv + tid];
    red[tid] = v;
    __syncthreads();
    for (int o = 128; o; o >>= 1) {
        if (tid < o) red[tid] = fmaxf(red[tid], red[tid + o]);
        __syncthreads();
    }
    float smax = red[0];
    __syncthreads();
    float e = expf(v - smax);
    red[tid] = e;
    __syncthreads();
    for (int o = 128; o; o >>= 1) {
        if (tid < o) red[tid] += red[tid + o];
        __syncthreads();
    }
    d_alpha[b * Sv + tid] = e / red[0];
}

__global__ void outvec_kernel() {
    int b = blockIdx.x;
    int h = threadIdx.x;
    if (h >= H2) return;
    float a = 0.f;
    for (int s = 0; s < Sv; s++) a += d_alpha[b * Sv + s] * d_to[(size_t)(b * Sv + s) * H2 + h];
    d_ov[b * H2 + h] = a;
}

__global__ void final_fc(const float* __restrict__ fcW, const float* __restrict__ fcb,
                         float* __restrict__ out) {
    int b = blockIdx.x;
    int p = threadIdx.x >> 5;
    int lane = threadIdx.x & 31;
    if (p >= 3) return;
    float a = 0.f;
    for (int h = lane; h < H2; h += 32) a += d_ov[b * H2 + h] * fcW[h * 3 + p];
#pragma unroll
    for (int o = 16; o; o >>= 1) a += __shfl_down_sync(0xffffffffu, a, o);
    if (lane == 0) out[b * 3 + p] = a + fcb[p];
}

// ---------------- launch ----------------
extern "C" void kernel_launch(void* const* d_in, const int* in_sizes, int n_in,
                              void* d_out, int out_size) {
    const int* text_indices = (const int*)d_in[0];
    const int* aspect_indices = (const int*)d_in[1];
    const int* left_indices = (const int*)d_in[2];
    const int* head_vector = (const int*)d_in[4];
    const int* behead_vector = (const int*)d_in[5];
    const int* relation_vector = (const int*)d_in[6];
    const float* embed_table = (const float*)d_in[7];
    const float* rel_embed = (const float*)d_in[8];
    const float* Wf_ih = (const float*)d_in[9];
    const float* Wf_hh = (const float*)d_in[10];
    const float* bf = (const float*)d_in[11];
    const float* Wb_ih = (const float*)d_in[12];
    const float* Wb_hh = (const float*)d_in[13];
    const float* bb = (const float*)d_in[14];
    const float* bil_W = (const float*)d_in[15];
    const float* bil_b = (const float*)d_in[16];
    const float* gc1_W = (const float*)d_in[17];
    const float* gc1_b = (const float*)d_in[18];
    const float* gc2_W = (const float*)d_in[19];
    const float* gc2_b = (const float*)d_in[20];
    const float* fc_W = (const float*)d_in[21];
    const float* fc_b = (const float*)d_in[22];
    float* out = (float*)d_out;

    float* p_text;  cudaGetSymbolAddress((void**)&p_text, d_text);
    float* p_Xg;    cudaGetSymbolAddress((void**)&p_Xg, d_Xg);
    float* p_to;    cudaGetSymbolAddress((void**)&p_to, d_to);
    float* p_hid;   cudaGetSymbolAddress((void**)&p_hid, d_hid);
    float* p_x1;    cudaGetSymbolAddress((void**)&p_x1, d_x1);

    cudaFuncSetAttribute(lstm_persist, cudaFuncAttributeMaxDynamicSharedMemorySize,
                         LSTM_SMEM_BYTES);

    len_kernel<<<1, 64>>>(text_indices, aspect_indices, left_indices);
    embed_kernel<<<(Bv * Sv * Ev + 255) / 256, 256>>>(text_indices, embed_table);

    {
        dim3 g((G4 + 63) / 64, (Bv * Sv) / 128);
        mma_gemm<1, true, false><<<g, 256>>>(p_text, Wf_ih, bf, p_Xg, Bv * Sv, G4, Ev);
        mma_gemm<1, true, false><<<g, 256>>>(p_text, Wb_ih, bb,
                                             p_Xg + (size_t)Sv * Bv * G4, Bv * Sv, G4, Ev);
    }

    barr_reset<<<1, 512>>>();
    lstm_persist<<<2 * LSTM_BLOCKS_PER_DIR, LSTM_THREADS, LSTM_SMEM_BYTES>>>(Wf_hh, Wb_hh);

    assemble_to<<<(Bv * Sv * H2 + 255) / 256, 256>>>();

    vprep<<<NRELv, 256>>>(bil_W, rel_embed);
    relscore<<<(Bv * Rv) / 8, 256>>>(head_vector, behead_vector, relation_vector, bil_b);

    pwv_kernel<<<Bv, Sv>>>();

    {
        dim3 g((H2 + 63) / 64, (Bv * Sv) / 128);
        mma_gemm<0, false, true><<<g, 256>>>(p_to, gc1_W, nullptr, p_hid, Bv * Sv, H2, H2);
    }
    gcn_apply<<<Bv * Sv, 128>>>(head_vector, behead_vector, gc1_b, p_x1);

    {
        dim3 g((H2 + 63) / 64, (Bv * Sv) / 128);
        mma_gemm<0, false, true><<<g, 256>>>(p_x1, gc2_W, nullptr, p_hid, Bv * Sv, H2, H2);
    }
    gcn_apply<<<Bv * Sv, 128>>>(head_vector, behead_vector, gc2_b, p_x1);

    xsum_kernel<<<Bv, 640>>>(p_x1);
    attscore<<<(Bv * Sv) / 8, 256>>>();
    softmax_kernel<<<Bv, 256>>>();
    outvec_kernel<<<Bv, 640>>>();
    final_fc<<<Bv, 96>>>(fc_W, fc_b, out);

    (void)in_sizes; (void)n_in; (void)out_size;
}